// round 15
// baseline (speedup 1.0000x reference)
#include <cuda_runtime.h>
#include <cuda_fp16.h>
#include <cstdint>
#include <cstddef>

#define DEVINL __device__ __forceinline__

constexpr int MROWS = 16384;
constexpr int KTOT  = 1024;
constexpr int NCOLS = 1024;

constexpr int BM = 128, BN = 128, BK = 64;
constexpr int STAGES = 3;
constexpr int TPB = 256;
constexpr int KSPLIT = 2;
constexpr int NCHUNK_S = KTOT / BK / KSPLIT;    // 8 chunks per split-CTA
constexpr int NTILES = (MROWS / BM) * (NCOLS / BN);  // 1024

constexpr int A_BYTES = BM * BK * 2;            // 16 KB
constexpr int B_BYTES = BN * BK * 2;            // 16 KB
constexpr int STAGE_BYTES = A_BYTES + B_BYTES;  // 32 KB
constexpr int SMEM_TOTAL = STAGES * STAGE_BYTES; // 96 KB (x2 CTAs = 192 KB/SM)

// Static device scratch (allocation-free rule)
__device__ __half g_ah[(size_t)MROWS * KTOT];   // A converted to fp16
__device__ __half g_wt[(size_t)NCOLS * KTOT];   // W quantized, [n][k] K-major
__device__ float  g_part[(size_t)KSPLIT * NTILES * (BM * BN)]; // split-K partials
__device__ unsigned g_cnt[NTILES];              // per-tile arrival counters

// prep split
constexpr int CONV_BLOCKS  = 4096;
constexpr int QUANT_BLOCKS = (NCOLS / 32) * (KTOT / 32);  // 1024
constexpr int CONV_STRIDE  = CONV_BLOCKS * 256;           // units of 8 floats

// ---------------------------------------------------------------- helpers
DEVINL uint32_t smem_u32(const void* p) {
    uint32_t r;
    asm("{ .reg .u64 t; cvta.to.shared.u64 t, %1; cvt.u32.u64 %0, t; }"
        : "=r"(r) : "l"(p));
    return r;
}
DEVINL uint32_t swz(uint32_t off) { return off ^ ((off >> 3) & 0x70); }
DEVINL void cp_async16(uint32_t s, const void* g) {
    asm volatile("cp.async.cg.shared.global [%0], [%1], 16;"
                 :: "r"(s), "l"(g) : "memory");
}
DEVINL void cp_commit() { asm volatile("cp.async.commit_group;" ::: "memory"); }
template <int N> DEVINL void cp_wait() {
    asm volatile("cp.async.wait_group %0;" :: "n"(N) : "memory");
}
DEVINL void ldsm_x4(uint32_t* r, uint32_t addr) {
    asm volatile("ldmatrix.sync.aligned.m8n8.x4.shared.b16 {%0,%1,%2,%3}, [%4];"
                 : "=r"(r[0]), "=r"(r[1]), "=r"(r[2]), "=r"(r[3]) : "r"(addr));
}
DEVINL void mma16816(float* c, const uint32_t* a, const uint32_t* b) {
    asm volatile(
        "mma.sync.aligned.m16n8k16.row.col.f32.f16.f16.f32 "
        "{%0,%1,%2,%3}, {%4,%5,%6,%7}, {%8,%9}, {%0,%1,%2,%3};"
        : "+f"(c[0]), "+f"(c[1]), "+f"(c[2]), "+f"(c[3])
        : "r"(a[0]), "r"(a[1]), "r"(a[2]), "r"(a[3]), "r"(b[0]), "r"(b[1]));
}
DEVINL uint32_t pack_half2(float x, float y) {
    __half2 h = __floats2half2_rn(x, y);
    return *reinterpret_cast<uint32_t*>(&h);
}
DEVINL void ldg128nc(float4& v, const float* p) {
    asm volatile("ld.global.nc.v4.f32 {%0,%1,%2,%3}, [%4];"
                 : "=f"(v.x), "=f"(v.y), "=f"(v.z), "=f"(v.w) : "l"(p));
}
DEVINL void ldg128cg(float4& v, const float* p) {
    asm volatile("ld.global.cg.v4.f32 {%0,%1,%2,%3}, [%4];"
                 : "=f"(v.x), "=f"(v.y), "=f"(v.z), "=f"(v.w) : "l"(p));
}
DEVINL void stg128cs(void* p, uint32_t x, uint32_t y, uint32_t z, uint32_t w) {
    asm volatile("st.global.cs.v4.b32 [%0], {%1,%2,%3,%4};"
                 :: "l"(p), "r"(x), "r"(y), "r"(z), "r"(w) : "memory");
}

// -------------------------------------------- merged prep kernel
__global__ void prep_kernel(const float* __restrict__ a,
                            const float* __restrict__ w) {
    const int bid = blockIdx.x;
    const int t   = threadIdx.x;

    if (bid < CONV_BLOCKS) {
        if (bid == 0) {                         // reset split-K counters
            #pragma unroll
            for (int i = 0; i < NTILES / 256; i++) g_cnt[t + i * 256] = 0;
        }
        const size_t u0 = (size_t)bid * 256 + t;
        const size_t u1 = u0 + CONV_STRIDE;
        const float* p0 = a + u0 * 8;
        const float* p1 = a + u1 * 8;
        float4 v0a, v0b, v1a, v1b;
        ldg128nc(v0a, p0);
        ldg128nc(v0b, p0 + 4);
        ldg128nc(v1a, p1);
        ldg128nc(v1b, p1 + 4);
        stg128cs(g_ah + u0 * 8,
                 pack_half2(v0a.x, v0a.y), pack_half2(v0a.z, v0a.w),
                 pack_half2(v0b.x, v0b.y), pack_half2(v0b.z, v0b.w));
        stg128cs(g_ah + u1 * 8,
                 pack_half2(v1a.x, v1a.y), pack_half2(v1a.z, v1a.w),
                 pack_half2(v1b.x, v1b.y), pack_half2(v1b.z, v1b.w));
    } else {
        __shared__ __half tile[32][33];
        const int tb = bid - CONV_BLOCKS;
        const int n0 = (tb & 31) * 32;
        const int k0 = (tb >> 5) * 32;
        const int tx = t & 31;
        const int ty = t >> 5;
        #pragma unroll
        for (int i = ty; i < 32; i += 8) {
            float x = w[(size_t)(k0 + i) * NCOLS + n0 + tx];
            x = fminf(fmaxf(x, -0.5f), 0.5f);
            float y = rintf(x * 2.0f) * 0.5f;
            tile[i][tx] = __float2half_rn(y);
        }
        __syncthreads();
        #pragma unroll
        for (int i = ty; i < 32; i += 8)
            g_wt[(size_t)(n0 + i) * KTOT + k0 + tx] = tile[tx][i];
    }
}

// ------------------------------------------------------------- main GEMM
// R4 mainloop, split-K=2; last-finisher-merges epilogue (no waiting).
__global__ void __launch_bounds__(TPB, 2)
gemm_hmma_kernel(float* __restrict__ C) {
    extern __shared__ char smem[];
    __shared__ unsigned s_old;
    const uint32_t sb = smem_u32(smem);
    const int tid  = threadIdx.x;
    const int lane = tid & 31;
    const int wid  = tid >> 5;
    const int warpM = wid & 3;
    const int warpN = wid >> 2;

    const int m0 = blockIdx.y * BM;
    const int n0 = blockIdx.x * BN;
    const int zz = blockIdx.z;                 // k-half 0/1
    const int tileId = blockIdx.y * 8 + blockIdx.x;

    const char* aG = (const char*)(g_ah + (size_t)m0 * KTOT + zz * (KTOT / 2));
    const char* bG = (const char*)(g_wt + (size_t)n0 * KTOT + zz * (KTOT / 2));

    const int lr = tid >> 3;
    const int lc = (tid & 7) * 16;
    const uint32_t ld_sw0 = swz(lr * 128 + lc);

    auto load_stage = [&](int kc, int s) {
        const uint32_t aS = sb + s * STAGE_BYTES;
        const uint32_t bS = aS + A_BYTES;
        const char* ag = aG + (size_t)lr * (KTOT * 2) + kc * (BK * 2) + lc;
        const char* bg = bG + (size_t)lr * (KTOT * 2) + kc * (BK * 2) + lc;
        #pragma unroll
        for (int it = 0; it < 4; it++) {
            const uint32_t sw = ld_sw0 + it * 32 * 128;
            cp_async16(aS + sw, ag + (size_t)it * 32 * KTOT * 2);
            cp_async16(bS + sw, bg + (size_t)it * 32 * KTOT * 2);
        }
    };

    uint32_t aBase[2], bBase[4];
    #pragma unroll
    for (int mi = 0; mi < 2; mi++) {
        const int row = warpM * 32 + mi * 16 + (lane & 15);
        const int ko  = (lane >> 4) * 8;
        aBase[mi] = swz(row * 128 + ko * 2);
    }
    #pragma unroll
    for (int nj = 0; nj < 4; nj++) {
        const int row = warpN * 64 + nj * 16 + ((lane >> 4) << 3) + (lane & 7);
        const int ko  = ((lane >> 3) & 1) * 8;
        bBase[nj] = swz(row * 128 + ko * 2) + A_BYTES;
    }

    #pragma unroll
    for (int s = 0; s < STAGES - 1; s++) {
        load_stage(s, s);
        cp_commit();
    }

    float acc[2][8][4] = {};

    for (int kc = 0; kc < NCHUNK_S; kc++) {
        cp_wait<STAGES - 2>();
        __syncthreads();

        if (kc + STAGES - 1 < NCHUNK_S)
            load_stage(kc + STAGES - 1, (kc + STAGES - 1) % STAGES);
        cp_commit();

        const uint32_t stS = sb + (kc % STAGES) * STAGE_BYTES;

        #pragma unroll
        for (int ki = 0; ki < BK / 16; ki++) {
            const uint32_t kOff = ki * 32;
            uint32_t afr[2][4], bfr[4][4];
            #pragma unroll
            for (int mi = 0; mi < 2; mi++)
                ldsm_x4(afr[mi], stS + (aBase[mi] ^ kOff));
            #pragma unroll
            for (int nj = 0; nj < 4; nj++)
                ldsm_x4(bfr[nj], stS + (bBase[nj] ^ kOff));
            #pragma unroll
            for (int mi = 0; mi < 2; mi++)
                #pragma unroll
                for (int nj = 0; nj < 8; nj++)
                    mma16816(acc[mi][nj], afr[mi], &bfr[nj >> 1][(nj & 1) * 2]);
        }
    }

    // ---- split-K epilogue: publish my partial, last finisher merges
    float* af = &acc[0][0][0];                  // 64 floats, fragment order
    float* slot = g_part + ((size_t)(zz * NTILES + tileId)) * (BM * BN);
    #pragma unroll
    for (int i = 0; i < 16; i++) {              // coalesced 512B/warp stores
        *reinterpret_cast<float4*>(slot + i * 1024 + tid * 4) =
            make_float4(af[4 * i], af[4 * i + 1], af[4 * i + 2], af[4 * i + 3]);
    }
    __threadfence();
    __syncthreads();
    if (tid == 0) {
        unsigned old;
        asm volatile("atom.acq_rel.gpu.global.add.u32 %0, [%1], %2;"
                     : "=r"(old) : "l"(g_cnt + tileId), "r"(1u) : "memory");
        s_old = old;
    }
    __syncthreads();
    if (s_old == 0) return;                     // first finisher: done

    // last finisher: add partner's partial (already published), write C
    const float* ps = g_part + ((size_t)((zz ^ 1) * NTILES + tileId)) * (BM * BN);
    #pragma unroll
    for (int i = 0; i < 16; i++) {
        float4 v;
        ldg128cg(v, ps + i * 1024 + tid * 4);
        af[4 * i]     += v.x;
        af[4 * i + 1] += v.y;
        af[4 * i + 2] += v.z;
        af[4 * i + 3] += v.w;
    }

    float* cBase = C + (size_t)(m0 + warpM * 32) * NCOLS + n0 + warpN * 64;
    const int cr = lane >> 2;
    const int cc = (lane & 3) * 2;
    #pragma unroll
    for (int mi = 0; mi < 2; mi++) {
        #pragma unroll
        for (int nj = 0; nj < 8; nj++) {
            float* p0 = cBase + (size_t)(mi * 16 + cr) * NCOLS + nj * 8 + cc;
            float* p1 = p0 + 8 * NCOLS;
            *reinterpret_cast<float2*>(p0) = make_float2(acc[mi][nj][0], acc[mi][nj][1]);
            *reinterpret_cast<float2*>(p1) = make_float2(acc[mi][nj][2], acc[mi][nj][3]);
        }
    }
}

// ---------------------------------------------------------------- launch
extern "C" void kernel_launch(void* const* d_in, const int* in_sizes, int n_in,
                              void* d_out, int out_size) {
    (void)in_sizes; (void)n_in; (void)out_size;
    const float* A = (const float*)d_in[0];   // [16384, 1024] fp32
    const float* W = (const float*)d_in[1];   // [1024, 1024] fp32
    float* C = (float*)d_out;                 // [16384, 1024] fp32

    prep_kernel<<<CONV_BLOCKS + QUANT_BLOCKS, 256>>>(A, W);

    cudaFuncSetAttribute(gemm_hmma_kernel,
                         cudaFuncAttributeMaxDynamicSharedMemorySize, SMEM_TOTAL);
    gemm_hmma_kernel<<<dim3(NCOLS / BN, MROWS / BM, KSPLIT), TPB, SMEM_TOTAL>>>(C);
}

// round 16
// speedup vs baseline: 1.3145x; 1.3145x over previous
#include <cuda_runtime.h>
#include <cuda_fp16.h>
#include <cstdint>
#include <cstddef>

#define DEVINL __device__ __forceinline__

constexpr int MROWS = 16384;
constexpr int KTOT  = 1024;
constexpr int NCOLS = 1024;

constexpr int BM = 128, BN = 128, BK = 64;
constexpr int STAGES = 3;
constexpr int TPB = 256;
constexpr int NCHUNK = KTOT / BK;               // 16
constexpr int NPANEL = MROWS / BM;              // 128 (also # converter CTAs)

constexpr int A_BYTES = BM * BK * 2;            // 16 KB
constexpr int B_BYTES = BN * BK * 2;            // 16 KB
constexpr int STAGE_BYTES = A_BYTES + B_BYTES;  // 32 KB
constexpr int SMEM_TOTAL = STAGES * STAGE_BYTES; // 96 KB (x2 CTAs = 192 KB/SM)

// Static device scratch (allocation-free rule)
__device__ __half g_ah[(size_t)MROWS * KTOT];   // A fp16 (written by conv CTAs)
__device__ __half g_wt[(size_t)NCOLS * KTOT];   // W quantized, [n][k] K-major
__device__ unsigned g_pf[NPANEL];               // panel-ready flags

// ---------------------------------------------------------------- helpers
DEVINL uint32_t smem_u32(const void* p) {
    uint32_t r;
    asm("{ .reg .u64 t; cvta.to.shared.u64 t, %1; cvt.u32.u64 %0, t; }"
        : "=r"(r) : "l"(p));
    return r;
}
DEVINL uint32_t swz(uint32_t off) { return off ^ ((off >> 3) & 0x70); }
DEVINL void cp_async16(uint32_t s, const void* g) {
    asm volatile("cp.async.cg.shared.global [%0], [%1], 16;"
                 :: "r"(s), "l"(g) : "memory");
}
DEVINL void cp_commit() { asm volatile("cp.async.commit_group;" ::: "memory"); }
template <int N> DEVINL void cp_wait() {
    asm volatile("cp.async.wait_group %0;" :: "n"(N) : "memory");
}
DEVINL void ldsm_x4(uint32_t* r, uint32_t addr) {
    asm volatile("ldmatrix.sync.aligned.m8n8.x4.shared.b16 {%0,%1,%2,%3}, [%4];"
                 : "=r"(r[0]), "=r"(r[1]), "=r"(r[2]), "=r"(r[3]) : "r"(addr));
}
DEVINL void mma16816(float* c, const uint32_t* a, const uint32_t* b) {
    asm volatile(
        "mma.sync.aligned.m16n8k16.row.col.f32.f16.f16.f32 "
        "{%0,%1,%2,%3}, {%4,%5,%6,%7}, {%8,%9}, {%0,%1,%2,%3};"
        : "+f"(c[0]), "+f"(c[1]), "+f"(c[2]), "+f"(c[3])
        : "r"(a[0]), "r"(a[1]), "r"(a[2]), "r"(a[3]), "r"(b[0]), "r"(b[1]));
}
DEVINL uint32_t pack_half2(float x, float y) {
    __half2 h = __floats2half2_rn(x, y);
    return *reinterpret_cast<uint32_t*>(&h);
}
DEVINL void ldg128nc(float4& v, const float* p) {
    asm volatile("ld.global.nc.v4.f32 {%0,%1,%2,%3}, [%4];"
                 : "=f"(v.x), "=f"(v.y), "=f"(v.z), "=f"(v.w) : "l"(p));
}
DEVINL void stg128cs(void* p, uint32_t x, uint32_t y, uint32_t z, uint32_t w) {
    asm volatile("st.global.cs.v4.b32 [%0], {%1,%2,%3,%4};"
                 :: "l"(p), "r"(x), "r"(y), "r"(z), "r"(w) : "memory");
}
DEVINL unsigned flag_ld_acq(const unsigned* p) {
    unsigned v;
    asm volatile("ld.acquire.gpu.global.u32 %0, [%1];" : "=r"(v) : "l"(p) : "memory");
    return v;
}
DEVINL void flag_st_rel(unsigned* p) {
    asm volatile("st.release.gpu.global.u32 [%0], 1;" :: "l"(p) : "memory");
}

// -------------------------------------------- W quantize + flag reset (tiny)
__global__ void quant_w_kernel(const float* __restrict__ w) {
    if (blockIdx.x == 0 && threadIdx.x < NPANEL) g_pf[threadIdx.x] = 0;
    __shared__ __half tile[32][33];
    const int n0 = (blockIdx.x & 31) * 32;
    const int k0 = (blockIdx.x >> 5) * 32;
    const int tx = threadIdx.x & 31;
    const int ty = threadIdx.x >> 5;
    #pragma unroll
    for (int i = ty; i < 32; i += 8) {
        float x = w[(size_t)(k0 + i) * NCOLS + n0 + tx];
        x = fminf(fmaxf(x, -0.5f), 0.5f);     // clip [-1+delta, 1-delta]
        float y = rintf(x * 2.0f) * 0.5f;     // round-half-even, step 0.5
        tile[i][tx] = __float2half_rn(y);     // exact in fp16
    }
    __syncthreads();
    #pragma unroll
    for (int i = ty; i < 32; i += 8)
        g_wt[(size_t)(n0 + i) * KTOT + k0 + tx] = tile[tx][i];
}

// ------------------------------------------------------------- fused kernel
// bids [0,128): converter CTAs (guaranteed wave-1 resident: 128 < 296 slots).
// bids [128, 128+1024): GEMM CTAs — exact R4 body after one panel-flag wait.
__global__ void __launch_bounds__(TPB, 2)
fused_kernel(const float* __restrict__ Afp32, float* __restrict__ C) {
    const int tid = threadIdx.x;

    if (blockIdx.x < NPANEL) {
        // ---- converter CTA: panel p = blockIdx.x (128 rows of A)
        const int p = blockIdx.x;
        const float* src = Afp32 + (size_t)p * BM * KTOT;
        __half*      dst = g_ah  + (size_t)p * BM * KTOT;
        // 128*1024 fp32 = 16384 units of 8; 64 units/thread, 4-deep MLP
        #pragma unroll 1
        for (int i = 0; i < 16; i++) {
            const size_t u = (size_t)tid + (size_t)i * 1024;  // 4 units per iter
            float4 a0, a1, b0, b1, c0, c1, d0, d1;
            ldg128nc(a0, src + (u)        * 8); ldg128nc(a1, src + (u)        * 8 + 4);
            ldg128nc(b0, src + (u + 256)  * 8); ldg128nc(b1, src + (u + 256)  * 8 + 4);
            ldg128nc(c0, src + (u + 512)  * 8); ldg128nc(c1, src + (u + 512)  * 8 + 4);
            ldg128nc(d0, src + (u + 768)  * 8); ldg128nc(d1, src + (u + 768)  * 8 + 4);
            stg128cs(dst + (u)       * 8, pack_half2(a0.x, a0.y), pack_half2(a0.z, a0.w),
                                          pack_half2(a1.x, a1.y), pack_half2(a1.z, a1.w));
            stg128cs(dst + (u + 256) * 8, pack_half2(b0.x, b0.y), pack_half2(b0.z, b0.w),
                                          pack_half2(b1.x, b1.y), pack_half2(b1.z, b1.w));
            stg128cs(dst + (u + 512) * 8, pack_half2(c0.x, c0.y), pack_half2(c0.z, c0.w),
                                          pack_half2(c1.x, c1.y), pack_half2(c1.z, c1.w));
            stg128cs(dst + (u + 768) * 8, pack_half2(d0.x, d0.y), pack_half2(d0.z, d0.w),
                                          pack_half2(d1.x, d1.y), pack_half2(d1.z, d1.w));
        }
        __threadfence();                        // publish STGs gpu-wide
        __syncthreads();                        // all threads fenced
        if (tid == 0) flag_st_rel(&g_pf[p]);
        return;                                 // free the slot
    }

    // ---- GEMM CTA (exact R4 body)
    extern __shared__ char smem[];
    const uint32_t sb = smem_u32(smem);
    const int lane = tid & 31;
    const int wid  = tid >> 5;
    const int warpM = wid & 3;
    const int warpN = wid >> 2;

    const int tileId = blockIdx.x - NPANEL;
    const int xT = tileId & 7;                  // x-fast: A-panel L2 reuse
    const int yT = tileId >> 3;
    const int m0 = yT * BM;
    const int n0 = xT * BN;

    // wait for this panel's fp16 data (producer is a lower-bid CTA: no deadlock)
    if (tid == 0) {
        if (!flag_ld_acq(&g_pf[yT]))
            while (!flag_ld_acq(&g_pf[yT])) __nanosleep(256);
    }
    __syncthreads();                            // acquire propagates block-wide

    const char* aG = (const char*)(g_ah + (size_t)m0 * KTOT);
    const char* bG = (const char*)(g_wt + (size_t)n0 * KTOT);

    const int lr = tid >> 3;
    const int lc = (tid & 7) * 16;
    const uint32_t ld_sw0 = swz(lr * 128 + lc);

    auto load_stage = [&](int kc, int s) {
        const uint32_t aS = sb + s * STAGE_BYTES;
        const uint32_t bS = aS + A_BYTES;
        const char* ag = aG + (size_t)lr * (KTOT * 2) + kc * (BK * 2) + lc;
        const char* bg = bG + (size_t)lr * (KTOT * 2) + kc * (BK * 2) + lc;
        #pragma unroll
        for (int it = 0; it < 4; it++) {
            const uint32_t sw = ld_sw0 + it * 32 * 128;
            cp_async16(aS + sw, ag + (size_t)it * 32 * KTOT * 2);
            cp_async16(bS + sw, bg + (size_t)it * 32 * KTOT * 2);
        }
    };

    uint32_t aBase[2], bBase[4];
    #pragma unroll
    for (int mi = 0; mi < 2; mi++) {
        const int row = warpM * 32 + mi * 16 + (lane & 15);
        const int ko  = (lane >> 4) * 8;
        aBase[mi] = swz(row * 128 + ko * 2);
    }
    #pragma unroll
    for (int nj = 0; nj < 4; nj++) {
        const int row = warpN * 64 + nj * 16 + ((lane >> 4) << 3) + (lane & 7);
        const int ko  = ((lane >> 3) & 1) * 8;
        bBase[nj] = swz(row * 128 + ko * 2) + A_BYTES;
    }

    #pragma unroll
    for (int s = 0; s < STAGES - 1; s++) {
        load_stage(s, s);
        cp_commit();
    }

    float acc[2][8][4] = {};

    for (int kc = 0; kc < NCHUNK; kc++) {
        cp_wait<STAGES - 2>();
        __syncthreads();

        if (kc + STAGES - 1 < NCHUNK)
            load_stage(kc + STAGES - 1, (kc + STAGES - 1) % STAGES);
        cp_commit();

        const uint32_t stS = sb + (kc % STAGES) * STAGE_BYTES;

        #pragma unroll
        for (int ki = 0; ki < BK / 16; ki++) {
            const uint32_t kOff = ki * 32;
            uint32_t afr[2][4], bfr[4][4];
            #pragma unroll
            for (int mi = 0; mi < 2; mi++)
                ldsm_x4(afr[mi], stS + (aBase[mi] ^ kOff));
            #pragma unroll
            for (int nj = 0; nj < 4; nj++)
                ldsm_x4(bfr[nj], stS + (bBase[nj] ^ kOff));
            #pragma unroll
            for (int mi = 0; mi < 2; mi++)
                #pragma unroll
                for (int nj = 0; nj < 8; nj++)
                    mma16816(acc[mi][nj], afr[mi], &bfr[nj >> 1][(nj & 1) * 2]);
        }
    }

    float* cBase = C + (size_t)(m0 + warpM * 32) * NCOLS + n0 + warpN * 64;
    const int cr = lane >> 2;
    const int cc = (lane & 3) * 2;
    #pragma unroll
    for (int mi = 0; mi < 2; mi++) {
        #pragma unroll
        for (int nj = 0; nj < 8; nj++) {
            float* p0 = cBase + (size_t)(mi * 16 + cr) * NCOLS + nj * 8 + cc;
            float* p1 = p0 + 8 * NCOLS;
            *reinterpret_cast<float2*>(p0) = make_float2(acc[mi][nj][0], acc[mi][nj][1]);
            *reinterpret_cast<float2*>(p1) = make_float2(acc[mi][nj][2], acc[mi][nj][3]);
        }
    }
}

// ---------------------------------------------------------------- launch
extern "C" void kernel_launch(void* const* d_in, const int* in_sizes, int n_in,
                              void* d_out, int out_size) {
    (void)in_sizes; (void)n_in; (void)out_size;
    const float* A = (const float*)d_in[0];   // [16384, 1024] fp32
    const float* W = (const float*)d_in[1];   // [1024, 1024] fp32
    float* C = (float*)d_out;                 // [16384, 1024] fp32

    quant_w_kernel<<<(NCOLS / 32) * (KTOT / 32), 256>>>(W);

    cudaFuncSetAttribute(fused_kernel,
                         cudaFuncAttributeMaxDynamicSharedMemorySize, SMEM_TOTAL);
    fused_kernel<<<NPANEL + (NCOLS / BN) * (MROWS / BM), TPB, SMEM_TOTAL>>>(A, C);
}